// round 2
// baseline (speedup 1.0000x reference)
#include <cuda_runtime.h>
#include <math.h>
#include <stdint.h>

// ---------------------------------------------------------------------------
// Gate_14293651161746: DeepSeek-style sigmoid router
//   logits[T,E] = x[T,D] @ W[E,D]^T   (fp32)
//   scores = sigmoid(logits); s = scores + bias
//   groups of 32 (G=8): group_score = sum(top2(s_g))
//   keep top-4 groups; masked s (others -> 0.0)
//   top-8 experts over masked s (stable ties: smaller index first)
//   weights = scores[idx] / sum * 2.5
// Output: [weights (T*8) fp32][indices (T*8) as fp32]
// ---------------------------------------------------------------------------

#define MAX_T 8192
#define MAX_E 256

static __device__ float g_logits[MAX_T * MAX_E];  // 8 MB scratch

// ------------------------------ SGEMM (NT) ---------------------------------
// C[t][e] = sum_d A[t][d] * B[e][d]; A row-major [T,D], B row-major [E,D].
#define BM 128
#define BN 128
#define BK 16
#define TM 8
#define TN 8

__global__ void __launch_bounds__(256, 1)
sgemm_nt_kernel(const float* __restrict__ A, const float* __restrict__ B,
                float* __restrict__ C, int T, int E, int D) {
    __shared__ float As[BK][BM + 4];
    __shared__ float Bs[BK][BN + 4];

    const int bm = blockIdx.x * BM;
    const int bn = blockIdx.y * BN;
    const int tid = threadIdx.x;
    const int tx = tid & 15;   // 0..15
    const int ty = tid >> 4;   // 0..15

    float acc[TM][TN];
#pragma unroll
    for (int i = 0; i < TM; i++)
#pragma unroll
        for (int j = 0; j < TN; j++) acc[i][j] = 0.0f;

    for (int k0 = 0; k0 < D; k0 += BK) {
        // cooperative load: 128 rows x 16 cols = 512 float4 per operand
#pragma unroll
        for (int it = 0; it < 2; it++) {
            int f4 = tid + it * 256;       // 0..511
            int row = f4 >> 2;             // 0..127
            int c4 = f4 & 3;               // 0..3
            float4 av = *(const float4*)(A + (size_t)(bm + row) * D + k0 + c4 * 4);
            As[c4 * 4 + 0][row] = av.x;
            As[c4 * 4 + 1][row] = av.y;
            As[c4 * 4 + 2][row] = av.z;
            As[c4 * 4 + 3][row] = av.w;
            float4 bv = *(const float4*)(B + (size_t)(bn + row) * D + k0 + c4 * 4);
            Bs[c4 * 4 + 0][row] = bv.x;
            Bs[c4 * 4 + 1][row] = bv.y;
            Bs[c4 * 4 + 2][row] = bv.z;
            Bs[c4 * 4 + 3][row] = bv.w;
        }
        __syncthreads();

#pragma unroll
        for (int kk = 0; kk < BK; kk++) {
            float a[TM], b[TN];
            float4 a0 = *(const float4*)&As[kk][ty * TM];
            float4 a1 = *(const float4*)&As[kk][ty * TM + 4];
            a[0] = a0.x; a[1] = a0.y; a[2] = a0.z; a[3] = a0.w;
            a[4] = a1.x; a[5] = a1.y; a[6] = a1.z; a[7] = a1.w;
            float4 b0 = *(const float4*)&Bs[kk][tx * TN];
            float4 b1 = *(const float4*)&Bs[kk][tx * TN + 4];
            b[0] = b0.x; b[1] = b0.y; b[2] = b0.z; b[3] = b0.w;
            b[4] = b1.x; b[5] = b1.y; b[6] = b1.z; b[7] = b1.w;
#pragma unroll
            for (int i = 0; i < TM; i++)
#pragma unroll
                for (int j = 0; j < TN; j++) acc[i][j] = fmaf(a[i], b[j], acc[i][j]);
        }
        __syncthreads();
    }

#pragma unroll
    for (int i = 0; i < TM; i++) {
        int row = bm + ty * TM + i;
#pragma unroll
        for (int j = 0; j < TN; j++) {
            int col = bn + tx * TN + j;
            C[(size_t)row * E + col] = acc[i][j];
        }
    }
}

// ------------------------------ gating stage -------------------------------
// One warp per token. Lane holds expert e = k*32 + lane for k=0..7, so its
// k-th value is exactly group k's member — group reductions are warp-wide.

#define FULLMASK 0xFFFFFFFFu

__global__ void __launch_bounds__(256)
gate_topk_kernel(const float* __restrict__ logits, const float* __restrict__ bias,
                 float* __restrict__ outW, float* __restrict__ outI, int T) {
    const int warp = (blockIdx.x * blockDim.x + threadIdx.x) >> 5;
    const int lane = threadIdx.x & 31;
    if (warp >= T) return;

    const float* L = logits + (size_t)warp * 256;

    float sig[8], s[8];
#pragma unroll
    for (int k = 0; k < 8; k++) {
        float lg = L[k * 32 + lane];
        float sg = 1.0f / (1.0f + expf(-lg));
        sig[k] = sg;
        s[k] = sg + bias[k * 32 + lane];
    }

    // group scores: sum of top-2 of s within each 32-lane group
    float gsc[8];
#pragma unroll
    for (int g = 0; g < 8; g++) {
        float bv = s[g];
        int bi = lane;
#pragma unroll
        for (int off = 16; off > 0; off >>= 1) {
            float ov = __shfl_xor_sync(FULLMASK, bv, off);
            int oi = __shfl_xor_sync(FULLMASK, bi, off);
            if (ov > bv || (ov == bv && oi < bi)) { bv = ov; bi = oi; }
        }
        float v2 = (lane == bi) ? -INFINITY : s[g];
#pragma unroll
        for (int off = 16; off > 0; off >>= 1)
            v2 = fmaxf(v2, __shfl_xor_sync(FULLMASK, v2, off));
        gsc[g] = bv + v2;
    }

    // top-4 groups (identical on every lane; strict > keeps lowest index on tie)
    bool keep[8];
#pragma unroll
    for (int g = 0; g < 8; g++) keep[g] = false;
#pragma unroll
    for (int r = 0; r < 4; r++) {
        float best = -INFINITY;
        int bg = 0;
#pragma unroll
        for (int g = 0; g < 8; g++)
            if (!keep[g] && gsc[g] > best) { best = gsc[g]; bg = g; }
        keep[bg] = true;
    }

    // masked scores (excluded groups -> exactly 0.0, matching sg*mask)
    float sm[8];
#pragma unroll
    for (int k = 0; k < 8; k++) sm[k] = keep[k] ? s[k] : 0.0f;

    // top-8 experts with stable ties (value desc, global index asc)
    bool taken[8];
#pragma unroll
    for (int k = 0; k < 8; k++) taken[k] = false;

    float wsel[8];
    int isel[8];
    float wsum = 0.0f;
#pragma unroll
    for (int r = 0; r < 8; r++) {
        float bv = -INFINITY;
        int bi = 0x7FFFFFFF;
#pragma unroll
        for (int k = 0; k < 8; k++) {
            if (!taken[k]) {
                float v = sm[k];
                int idx = k * 32 + lane;
                if (v > bv || (v == bv && idx < bi)) { bv = v; bi = idx; }
            }
        }
#pragma unroll
        for (int off = 16; off > 0; off >>= 1) {
            float ov = __shfl_xor_sync(FULLMASK, bv, off);
            int oi = __shfl_xor_sync(FULLMASK, bi, off);
            if (ov > bv || (ov == bv && oi < bi)) { bv = ov; bi = oi; }
        }
        int wl = bi & 31;
        int wk = bi >> 5;
        if (lane == wl) taken[wk] = true;
        // pick sig[wk] without dynamic register indexing (wk is warp-uniform)
        float selv = sig[0];
#pragma unroll
        for (int k = 1; k < 8; k++)
            if (k == wk) selv = sig[k];
        float ws = __shfl_sync(FULLMASK, selv, wl);
        wsel[r] = ws;
        isel[r] = bi;
        wsum += ws;
    }

    if (lane == 0) {
        float inv = 1.0f / wsum;
#pragma unroll
        for (int r = 0; r < 8; r++) {
            float w = wsel[r] * inv;   // weights / sum
            w = w * 2.5f;              // * route_scale
            outW[(size_t)warp * 8 + r] = w;
            outI[(size_t)warp * 8 + r] = (float)isel[r];
        }
    }
}

// ------------------------------ launch -------------------------------------

extern "C" void kernel_launch(void* const* d_in, const int* in_sizes, int n_in,
                              void* d_out, int out_size) {
    const float* x = (const float*)d_in[0];       // [T, D]
    const float* weight = (const float*)d_in[1];  // [E, D]
    const float* bias = (const float*)d_in[2];    // [E]

    int E = in_sizes[2];                 // 256
    int D = in_sizes[1] / E;             // 7168
    int T = in_sizes[0] / D;             // 8192

    dim3 gg((T + BM - 1) / BM, (E + BN - 1) / BN);
    sgemm_nt_kernel<<<gg, 256>>>(x, weight, g_logits, T, E, D);

    float* outW = (float*)d_out;
    float* outI = (float*)d_out + (size_t)T * 8;  // indices stored as floats after weights

    int warps_per_block = 256 / 32;
    int blocks = (T + warps_per_block - 1) / warps_per_block;
    gate_topk_kernel<<<blocks, 256>>>(g_logits, bias, outW, outI, T);
}

// round 8
// speedup vs baseline: 3.2526x; 3.2526x over previous
#include <cuda_runtime.h>
#include <cuda_fp16.h>
#include <math.h>
#include <stdint.h>

// ---------------------------------------------------------------------------
// Gate_14293651161746 (round 8): fused fp16-split HMMA GEMM + in-SMEM gating.
//   logits = x[T,D] @ W[E,D]^T via scaled 2-term fp16 split.
//   B is pre-scaled by 64 (power of 2) so main AND residual planes are fp16
//   normal-range; residuals additionally scaled by 2048.
//     a = a0 + a1s/2048 ; 64*b = b0 + b1s/2048
//     accA = sum a0*b0 ; accB = sum (a0*b1s + a1s*b0)
//     logit = (accA + accB/2048) / 64, accumulated in fp32 SMEM in k=256 chunks
//   Each CTA: 64 tokens x 256 experts -> full gate computed in-SMEM.
// Output: [weights (T*8) fp32][indices (T*8) as fp32]
// ---------------------------------------------------------------------------

#define FULLMASK 0xFFFFFFFFu
#define RSCALE 2048.0f
#define RSCALE_INV (1.0f / 2048.0f)
#define BSCALE 64.0f
#define BSCALE_INV (1.0f / 64.0f)

// ---- SMEM layout ----------------------------------------------------------
// Stage buffer (fp16 tiles, rows padded to 40 halves = 80 B):
//   A0: 64 x 40 = 5120 B (off 0) | A1s: 5120 B (off 5120)
//   B0: 256 x 40 = 20480 B (off 10240) | B1s: 20480 B (off 30720)
// Two stages, then fp32 logits accumulator [64][264].
#define STAGE_BYTES 51200
#define LOGITS_OFF  102400
#define SMEM_BYTES  (102400 + 64 * 264 * 4)   // 169984

__device__ __forceinline__ uint32_t smem_to_u32(const void* p) {
    uint32_t a;
    asm("{ .reg .u64 t; cvta.to.shared.u64 t, %1; cvt.u32.u64 %0, t; }" : "=r"(a) : "l"(p));
    return a;
}

#define LDM4(r, addr) \
    asm volatile("ldmatrix.sync.aligned.m8n8.x4.shared.b16 {%0,%1,%2,%3}, [%4];" \
                 : "=r"((r)[0]), "=r"((r)[1]), "=r"((r)[2]), "=r"((r)[3]) \
                 : "r"(addr))

#define MMA16816(c, a, b0, b1) \
    asm volatile("mma.sync.aligned.m16n8k16.row.col.f32.f16.f16.f32 " \
                 "{%0,%1,%2,%3}, {%4,%5,%6,%7}, {%8,%9}, {%0,%1,%2,%3};" \
                 : "+f"((c)[0]), "+f"((c)[1]), "+f"((c)[2]), "+f"((c)[3]) \
                 : "r"((a)[0]), "r"((a)[1]), "r"((a)[2]), "r"((a)[3]), \
                   "r"(b0), "r"(b1))

// split one float4 (optionally pre-scaled) into main fp16 quad + scaled-residual quad
__device__ __forceinline__ void split4s(float4 v, float pre, uint2& lo, uint2& hi) {
    float vx = v.x * pre, vy = v.y * pre, vz = v.z * pre, vw = v.w * pre;
    __half a0 = __float2half_rn(vx), b0 = __float2half_rn(vy);
    __half c0 = __float2half_rn(vz), d0 = __float2half_rn(vw);
    __half a1 = __float2half_rn((vx - __half2float(a0)) * RSCALE);
    __half b1 = __float2half_rn((vy - __half2float(b0)) * RSCALE);
    __half c1 = __float2half_rn((vz - __half2float(c0)) * RSCALE);
    __half d1 = __float2half_rn((vw - __half2float(d0)) * RSCALE);
    lo.x = (uint32_t)__half_as_ushort(a0) | ((uint32_t)__half_as_ushort(b0) << 16);
    lo.y = (uint32_t)__half_as_ushort(c0) | ((uint32_t)__half_as_ushort(d0) << 16);
    hi.x = (uint32_t)__half_as_ushort(a1) | ((uint32_t)__half_as_ushort(b1) << 16);
    hi.y = (uint32_t)__half_as_ushort(c1) | ((uint32_t)__half_as_ushort(d1) << 16);
}

__global__ void __launch_bounds__(256, 1)
moe_gate_kernel(const float* __restrict__ X, const float* __restrict__ Wt,
                const float* __restrict__ bias, float* __restrict__ outW,
                float* __restrict__ outI, int T, int E, int D) {
    extern __shared__ char smem[];
    const uint32_t sb = smem_to_u32(smem);
    const int tid = threadIdx.x;
    const int lane = tid & 31;
    const int wid = tid >> 5;
    const int wm = wid >> 2;   // 0..1  -> 32-row slice
    const int wn = wid & 3;    // 0..3  -> 64-col slice
    const int bm = blockIdx.x * 64;

    float* ls = (float*)(smem + LOGITS_OFF);   // [64][264] fp32 logits accumulator

    // zero logits accumulator
#pragma unroll
    for (int i = 0; i < 66; i++) ls[tid + i * 256] = 0.0f;

    float accA[2][8][4];
    float accB[2][8][4];
#pragma unroll
    for (int i = 0; i < 2; i++)
#pragma unroll
        for (int j = 0; j < 8; j++)
#pragma unroll
            for (int k = 0; k < 4; k++) { accA[i][j][k] = 0.0f; accB[i][j][k] = 0.0f; }

    // global staging: element i = tid + j*256; row = i>>3, chunk col = (i&7)*4
    const int grow = tid >> 3;
    const int gcol = (tid & 7) * 4;
    const float* Ag = X + (size_t)(bm + grow) * D + gcol;
    const float* Bg = Wt + (size_t)grow * D + gcol;
    const size_t jstride = (size_t)32 * D;

    const int NS = D / 32;
    float4 ra[2], rb[8];

    // ldmatrix per-thread base offsets (bytes within a stage buffer)
    const int q = lane >> 3;
    const uint32_t pa = (uint32_t)((wm * 32 + (q & 1) * 8 + (lane & 7)) * 80 + (q >> 1) * 16);
    const uint32_t pb = (uint32_t)((wn * 64 + ((q >> 1) & 1) * 8 + (lane & 7)) * 80 + (q & 1) * 16);

    // fragment element -> logits row/col (for chunk drains)
    const int drow = wm * 32 + (lane >> 2);
    const int dcol = wn * 64 + (lane & 3) * 2;

    // prologue LDG (stage 0)
#pragma unroll
    for (int j = 0; j < 2; j++) ra[j] = *(const float4*)(Ag + j * jstride);
#pragma unroll
    for (int j = 0; j < 8; j++) rb[j] = *(const float4*)(Bg + j * jstride);

    const uint32_t sts_off = (uint32_t)(grow * 80 + (tid & 7) * 8);

    for (int s = 0; s < NS; s++) {
        const uint32_t boff = (uint32_t)((s & 1) * STAGE_BYTES);
        // ---- STS: split fp32 -> fp16 main + scaled-residual tiles --------
        {
            char* bufc = smem + boff;
#pragma unroll
            for (int j = 0; j < 2; j++) {
                uint2 lo, hi;
                split4s(ra[j], 1.0f, lo, hi);
                uint32_t o = sts_off + (uint32_t)j * (32 * 80);
                *(uint2*)(bufc + o) = lo;           // A0
                *(uint2*)(bufc + 5120 + o) = hi;    // A1s
            }
#pragma unroll
            for (int j = 0; j < 8; j++) {
                uint2 lo, hi;
                split4s(rb[j], BSCALE, lo, hi);     // B pre-scaled by 64
                uint32_t o = sts_off + (uint32_t)j * (32 * 80);
                *(uint2*)(bufc + 10240 + o) = lo;   // B0
                *(uint2*)(bufc + 30720 + o) = hi;   // B1s
            }
        }
        __syncthreads();

        // ---- LDG next stage (in flight during MMA) -----------------------
        if (s + 1 < NS) {
            const int k0 = (s + 1) * 32;
#pragma unroll
            for (int j = 0; j < 2; j++) ra[j] = *(const float4*)(Ag + k0 + j * jstride);
#pragma unroll
            for (int j = 0; j < 8; j++) rb[j] = *(const float4*)(Bg + k0 + j * jstride);
        }

        // ---- MMA over this stage: 2 k16-steps ----------------------------
        const uint32_t abase = sb + boff + pa;
        const uint32_t bbase = sb + boff + 10240 + pb;
#pragma unroll
        for (int ks = 0; ks < 2; ks++) {
            uint32_t a0f[2][4], a1f[2][4];
#pragma unroll
            for (int mt = 0; mt < 2; mt++) {
                uint32_t aaddr = abase + (uint32_t)(mt * 1280 + ks * 32);
                LDM4(a0f[mt], aaddr);
                LDM4(a1f[mt], aaddr + 5120);
            }
#pragma unroll
            for (int np = 0; np < 4; np++) {
                uint32_t b0f[4], b1f[4];
                uint32_t baddr = bbase + (uint32_t)(np * 1280 + ks * 32);
                LDM4(b0f, baddr);
                LDM4(b1f, baddr + 20480);
#pragma unroll
                for (int mt = 0; mt < 2; mt++) {
                    MMA16816(accA[mt][2 * np],     a0f[mt], b0f[0], b0f[1]);
                    MMA16816(accA[mt][2 * np + 1], a0f[mt], b0f[2], b0f[3]);
                    MMA16816(accB[mt][2 * np],     a1f[mt], b0f[0], b0f[1]);
                    MMA16816(accB[mt][2 * np + 1], a1f[mt], b0f[2], b0f[3]);
                    MMA16816(accB[mt][2 * np],     a0f[mt], b1f[0], b1f[1]);
                    MMA16816(accB[mt][2 * np + 1], a0f[mt], b1f[2], b1f[3]);
                }
            }
        }

        // ---- chunk drain every 8 stages (k=256): acc -> fp32 SMEM --------
        if ((s & 7) == 7) {
#pragma unroll
            for (int mt = 0; mt < 2; mt++) {
#pragma unroll
                for (int np = 0; np < 4; np++) {
#pragma unroll
                    for (int nt = 0; nt < 2; nt++) {
                        float* cA = accA[mt][2 * np + nt];
                        float* cB = accB[mt][2 * np + nt];
                        int row = drow + mt * 16;
                        int col = dcol + np * 16 + nt * 8;
                        ls[row * 264 + col]           += cA[0] + cB[0] * RSCALE_INV;
                        ls[row * 264 + col + 1]       += cA[1] + cB[1] * RSCALE_INV;
                        ls[(row + 8) * 264 + col]     += cA[2] + cB[2] * RSCALE_INV;
                        ls[(row + 8) * 264 + col + 1] += cA[3] + cB[3] * RSCALE_INV;
                        cA[0] = cA[1] = cA[2] = cA[3] = 0.0f;
                        cB[0] = cB[1] = cB[2] = cB[3] = 0.0f;
                    }
                }
            }
        }
        __syncthreads();
    }

    // ---- gate: one warp per token, 8 tokens per warp ----------------------
    // lane l holds experts [8l..8l+7]; its group = l>>2 (experts/group = 32).
    float4 c0 = *(const float4*)(bias + lane * 8);
    float4 c1 = *(const float4*)(bias + lane * 8 + 4);
    const float bs[8] = {c0.x, c0.y, c0.z, c0.w, c1.x, c1.y, c1.z, c1.w};

    for (int r = 0; r < 8; r++) {
        const int tl = r * 8 + wid;
        const float* Lp = ls + tl * 264 + lane * 8;
        float4 v0 = *(const float4*)Lp;
        float4 v1 = *(const float4*)(Lp + 4);
        float lg[8] = {v0.x, v0.y, v0.z, v0.w, v1.x, v1.y, v1.z, v1.w};

        float sig[8], s[8];
#pragma unroll
        for (int j = 0; j < 8; j++) {
            float logit = lg[j] * BSCALE_INV;      // undo exact B pre-scale
            sig[j] = 1.0f / (1.0f + expf(-logit));
            s[j] = sig[j] + bs[j];
        }

        // per-lane top2, merged across the 4-lane quad (= one group)
        float t1 = -INFINITY, t2 = -INFINITY;
#pragma unroll
        for (int j = 0; j < 8; j++) {
            float v = s[j];
            if (v > t1) { t2 = t1; t1 = v; }
            else if (v > t2) { t2 = v; }
        }
#pragma unroll
        for (int off = 1; off < 4; off <<= 1) {
            float o1 = __shfl_xor_sync(FULLMASK, t1, off);
            float o2 = __shfl_xor_sync(FULLMASK, t2, off);
            float m1 = fmaxf(t1, o1);
            float m2 = fmaxf(fminf(t1, o1), (t1 > o1) ? t2 : o2);
            t1 = m1; t2 = m2;
        }
        float gsc = t1 + t2;

        float gs[8];
#pragma unroll
        for (int g = 0; g < 8; g++) gs[g] = __shfl_sync(FULLMASK, gsc, g * 4);

        // top-4 groups (lowest index wins ties, matching jax top_k)
        int keepmask = 0;
#pragma unroll
        for (int rr = 0; rr < 4; rr++) {
            float best = -INFINITY; int bg = 0;
#pragma unroll
            for (int g = 0; g < 8; g++)
                if (!((keepmask >> g) & 1) && gs[g] > best) { best = gs[g]; bg = g; }
            keepmask |= 1 << bg;
        }
        const bool mk = (keepmask >> (lane >> 2)) & 1;
        float sm[8];
#pragma unroll
        for (int j = 0; j < 8; j++) sm[j] = mk ? s[j] : 0.0f;

        // top-8 experts, stable (value desc, global index asc)
        int takenmask = 0;
        float wsel[8]; int isel[8]; float wsum = 0.0f;
#pragma unroll
        for (int rr = 0; rr < 8; rr++) {
            float bv = -INFINITY; int bi = 0x7FFFFFFF;
#pragma unroll
            for (int j = 0; j < 8; j++)
                if (!((takenmask >> j) & 1) && sm[j] > bv) { bv = sm[j]; bi = lane * 8 + j; }
#pragma unroll
            for (int off = 16; off > 0; off >>= 1) {
                float ov = __shfl_xor_sync(FULLMASK, bv, off);
                int oi = __shfl_xor_sync(FULLMASK, bi, off);
                if (ov > bv || (ov == bv && oi < bi)) { bv = ov; bi = oi; }
            }
            const int wl = bi >> 3, wj = bi & 7;
            if (lane == wl) takenmask |= 1 << wj;
            float selv = sig[0];
#pragma unroll
            for (int j = 1; j < 8; j++)
                if (j == wj) selv = sig[j];
            float wv = __shfl_sync(FULLMASK, selv, wl);
            wsel[rr] = wv; isel[rr] = bi; wsum += wv;
        }

        if (lane == 0) {
            const int token = bm + tl;
            float inv = 1.0f / wsum;
#pragma unroll
            for (int rr = 0; rr < 8; rr++) {
                outW[(size_t)token * 8 + rr] = wsel[rr] * inv * 2.5f;
                outI[(size_t)token * 8 + rr] = (float)isel[rr];
            }
        }
    }
}

// ------------------------------ launch -------------------------------------

extern "C" void kernel_launch(void* const* d_in, const int* in_sizes, int n_in,
                              void* d_out, int out_size) {
    const float* x = (const float*)d_in[0];       // [T, D]
    const float* weight = (const float*)d_in[1];  // [E, D]
    const float* bias = (const float*)d_in[2];    // [E]

    int E = in_sizes[2];           // 256
    int D = in_sizes[1] / E;       // 7168
    int T = in_sizes[0] / D;       // 8192

    float* outW = (float*)d_out;
    float* outI = (float*)d_out + (size_t)T * 8;

    cudaFuncSetAttribute(moe_gate_kernel, cudaFuncAttributeMaxDynamicSharedMemorySize,
                         SMEM_BYTES);
    moe_gate_kernel<<<T / 64, 256, SMEM_BYTES>>>(x, weight, bias, outW, outI, T, E, D);
}